// round 1
// baseline (speedup 1.0000x reference)
#include <cuda_runtime.h>
#include <cuda_bf16.h>
#include <math.h>

#define NN 50000
#define NEDGE 800000
#define D 256
#define NEXP 8
#define TOPK 3
#define TM 128
#define TN 128
#define KB 32

// ---------------- scratch (static device globals; no allocation) -------------
__device__ float g_agg[(size_t)NN * D];        // 51.2 MB aggregated features
__device__ int   g_gidx[NN * TOPK];            // top-3 expert ids per node
__device__ float g_gval[NN * TOPK];            // top-3 gate values per node
__device__ float g_imp[NEXP];                  // importance sums
__device__ int   g_load[NEXP];                 // selection counts (== load)
__device__ int   g_pos[NEXP];                  // running fill positions
__device__ int   g_off[NEXP + 1];              // per-expert list offsets
__device__ int   g_toff[NEXP + 1];             // per-expert tile offsets
__device__ int   g_perm[NN * TOPK];            // node ids grouped by expert
__device__ float g_permg[NN * TOPK];           // gate values aligned with perm
__device__ int   g_is32;                       // edge_index dtype flag

// ---------------- kernel 0: zero scratch + output, detect edge dtype ---------
__global__ void zero_kernel(float* __restrict__ y, const void* __restrict__ ei) {
    unsigned int i = blockIdx.x * blockDim.x + threadIdx.x;   // exactly NN*D threads
    g_agg[i] = 0.0f;
    y[i] = 0.0f;
    if (i < NEXP) { g_imp[i] = 0.0f; g_load[i] = 0; g_pos[i] = 0; }
    if (i == 0) {
        // If the buffer is int32, reading as u64 pairs two indices: value has a
        // nonzero high word almost surely (hi ~ U[0,50000), zero w.p. 2e-5).
        const unsigned long long* q = (const unsigned long long*)ei;
        int is32 = 0;
        #pragma unroll
        for (int k = 0; k < 8; k++)
            if (q[k] >= (unsigned long long)NN) is32 = 1;
        g_is32 = is32;
    }
}

// ---------------- kernel 1: edge scatter-add ---------------------------------
// task t -> edge t>>6, float4-chunk t&63. Block of 256 covers 4 edges exactly,
// so each warp's 32 lanes read/atomically-add a contiguous 512B span.
__global__ void scatter_kernel(const float* __restrict__ x, const void* __restrict__ eiv) {
    unsigned int t = blockIdx.x * blockDim.x + threadIdx.x;   // < NEDGE*64
    int e = t >> 6;
    int c = t & 63;
    long long s, dn;
    if (g_is32) {
        const int* p = (const int*)eiv;
        s  = p[e];
        dn = p[NEDGE + e];
    } else {
        const long long* p = (const long long*)eiv;
        s  = p[e];
        dn = p[NEDGE + e];
    }
    float4 v = __ldg((const float4*)(x + (size_t)s * D) + c);
    float* dst = g_agg + (size_t)dn * D + (size_t)c * 4;
    atomicAdd(dst + 0, v.x);
    atomicAdd(dst + 1, v.y);
    atomicAdd(dst + 2, v.z);
    atomicAdd(dst + 3, v.w);
}

// ---------------- kernel 2: gate (one warp per node) --------------------------
__global__ void gate_kernel(const float* __restrict__ Wg, const float* __restrict__ bg) {
    __shared__ float simp[NEXP];
    __shared__ int   scnt[NEXP];
    int tid = threadIdx.x;
    if (tid < NEXP) { simp[tid] = 0.0f; scnt[tid] = 0; }
    __syncthreads();

    int wid = tid >> 5, lane = tid & 31;
    int n = blockIdx.x * 8 + wid;
    if (n < NN) {
        const float* arow = g_agg + (size_t)n * D;
        float p[NEXP] = {0, 0, 0, 0, 0, 0, 0, 0};
        #pragma unroll
        for (int j = 0; j < 8; j++) {
            float a = arow[j * 32 + lane];
            const float* w = Wg + (size_t)(j * 32 + lane) * NEXP;
            #pragma unroll
            for (int e = 0; e < NEXP; e++) p[e] += a * __ldg(w + e);
        }
        #pragma unroll
        for (int e = 0; e < NEXP; e++) {
            #pragma unroll
            for (int off = 16; off; off >>= 1)
                p[e] += __shfl_xor_sync(0xffffffffu, p[e], off);
            p[e] = fmaxf(p[e] + __ldg(bg + e), 0.0f);   // relu(agg@W + b)
        }
        if (lane == 0) {
            float v[NEXP];
            #pragma unroll
            for (int e = 0; e < NEXP; e++) v[e] = p[e];
            int   idx[TOPK];
            float val[TOPK];
            #pragma unroll
            for (int k = 0; k < TOPK; k++) {            // strict '>' => lowest index on ties (matches top_k)
                int bi = 0; float bv = v[0];
                #pragma unroll
                for (int e = 1; e < NEXP; e++)
                    if (v[e] > bv) { bv = v[e]; bi = e; }
                idx[k] = bi; val[k] = bv; v[bi] = -1.0f; // relu values >= 0, so -1 excludes
            }
            float mx = val[0];
            float e0 = __expf(val[0] - mx), e1 = __expf(val[1] - mx), e2 = __expf(val[2] - mx);
            float inv = 1.0f / (e0 + e1 + e2);
            float gv[TOPK] = {e0 * inv, e1 * inv, e2 * inv};
            #pragma unroll
            for (int k = 0; k < TOPK; k++) {
                g_gidx[n * TOPK + k] = idx[k];
                g_gval[n * TOPK + k] = gv[k];
                atomicAdd(&simp[idx[k]], gv[k]);
                atomicAdd(&scnt[idx[k]], 1);
            }
        }
    }
    __syncthreads();
    if (tid < NEXP) {
        atomicAdd(&g_imp[tid], simp[tid]);
        atomicAdd(&g_load[tid], scnt[tid]);
    }
}

// ---------------- kernel 3: per-expert offsets --------------------------------
__global__ void offsets_kernel() {
    if (threadIdx.x == 0 && blockIdx.x == 0) {
        int o = 0, t = 0;
        for (int e = 0; e < NEXP; e++) {
            g_off[e]  = o;
            g_toff[e] = t;
            o += g_load[e];
            t += (g_load[e] + TM - 1) / TM;
        }
        g_off[NEXP]  = o;
        g_toff[NEXP] = t;
    }
}

// ---------------- kernel 4: build per-expert node lists -----------------------
__global__ void build_lists_kernel() {
    __shared__ int lc[NEXP];
    __shared__ int lb[NEXP];
    int tid = threadIdx.x;
    if (tid < NEXP) lc[tid] = 0;
    __syncthreads();

    int p = blockIdx.x * blockDim.x + tid;
    bool valid = (p < NN * TOPK);
    int e = 0, rank = 0, n = 0;
    float g = 0.0f;
    if (valid) {
        n = p / TOPK;
        e = g_gidx[p];
        g = g_gval[p];
        rank = atomicAdd(&lc[e], 1);
    }
    __syncthreads();
    if (tid < NEXP) lb[tid] = atomicAdd(&g_pos[tid], lc[tid]);
    __syncthreads();
    if (valid) {
        int slot = g_off[e] + lb[e] + rank;
        g_perm[slot]  = n;
        g_permg[slot] = g;
    }
}

// ---------------- kernel 5: grouped SGEMM + gated scatter epilogue ------------
// Per block: one expert tile [TM rows gathered via g_perm] x [TN output cols],
// K=256 in KB=32 steps. 256 threads, 8x8 register micro-tiles.
__global__ void __launch_bounds__(256, 2)
moe_gemm_kernel(const float* __restrict__ Wexp, const float* __restrict__ bexp,
                float* __restrict__ y) {
    __shared__ float sA[KB][TM];
    __shared__ float sB[KB][TN];

    int tile = blockIdx.x;
    if (tile >= g_toff[NEXP]) return;
    int e = 0;
    while (e < NEXP - 1 && tile >= g_toff[e + 1]) e++;
    int mt   = tile - g_toff[e];
    int base = g_off[e] + mt * TM;
    int rows = g_load[e] - mt * TM;
    if (rows > TM) rows = TM;
    int col0 = blockIdx.y * TN;

    int tid = threadIdx.x;
    int m      = tid & (TM - 1);   // A row owned by this thread for staging
    int k4base = tid >> 7;         // 0 or 1

    const float* Arow = nullptr;
    if (m < rows) Arow = g_agg + (size_t)g_perm[base + m] * D;
    const float* Wbase = Wexp + (size_t)e * D * D + col0;

    float acc[8][8];
    #pragma unroll
    for (int i = 0; i < 8; i++)
        #pragma unroll
        for (int j = 0; j < 8; j++) acc[i][j] = 0.0f;

    int tx = tid & 15, ty = tid >> 4;
    int tm = ty * 8,  tn = tx * 8;

    for (int k0 = 0; k0 < D; k0 += KB) {
        // stage A (gathered rows), transposed to sA[k][m]
        #pragma unroll
        for (int i = 0; i < 4; i++) {
            int k4 = k4base + 2 * i;
            float4 v = make_float4(0.f, 0.f, 0.f, 0.f);
            if (Arow) v = *(const float4*)(Arow + k0 + k4 * 4);
            sA[k4 * 4 + 0][m] = v.x;
            sA[k4 * 4 + 1][m] = v.y;
            sA[k4 * 4 + 2][m] = v.z;
            sA[k4 * 4 + 3][m] = v.w;
        }
        // stage B
        #pragma unroll
        for (int i = 0; i < 4; i++) {
            int idx = tid + i * 256;
            int n4 = idx & 31, kk = idx >> 5;
            float4 v = __ldg((const float4*)(Wbase + (size_t)(k0 + kk) * D + n4 * 4));
            *(float4*)&sB[kk][n4 * 4] = v;
        }
        __syncthreads();

        #pragma unroll
        for (int kk = 0; kk < KB; kk++) {
            float a[8], b[8];
            *(float4*)(a + 0) = *(const float4*)&sA[kk][tm + 0];
            *(float4*)(a + 4) = *(const float4*)&sA[kk][tm + 4];
            *(float4*)(b + 0) = *(const float4*)&sB[kk][tn + 0];
            *(float4*)(b + 4) = *(const float4*)&sB[kk][tn + 4];
            #pragma unroll
            for (int i = 0; i < 8; i++)
                #pragma unroll
                for (int j = 0; j < 8; j++)
                    acc[i][j] += a[i] * b[j];
        }
        __syncthreads();
    }

    // epilogue: y[node, col0+tn..] += g * (acc + b_e)
    #pragma unroll
    for (int im = 0; im < 8; im++) {
        int mm = tm + im;
        if (mm < rows) {
            int node = g_perm[base + mm];
            float gv = g_permg[base + mm];
            float* yrow = y + (size_t)node * D + col0 + tn;
            const float* brow = bexp + (size_t)e * D + col0 + tn;
            #pragma unroll
            for (int jn = 0; jn < 8; jn++)
                atomicAdd(yrow + jn, gv * (acc[im][jn] + __ldg(brow + jn)));
        }
    }
}

// ---------------- kernel 6: load-balancing loss -------------------------------
__global__ void loss_kernel(float* __restrict__ y, int out_size) {
    if (threadIdx.x == 0 && blockIdx.x == 0) {
        float mi = 0.0f, ml = 0.0f;
        for (int e = 0; e < NEXP; e++) { mi += g_imp[e]; ml += (float)g_load[e]; }
        mi *= (1.0f / NEXP);
        ml *= (1.0f / NEXP);
        float vi = 0.0f, vl = 0.0f;
        for (int e = 0; e < NEXP; e++) {
            float di = g_imp[e] - mi;         vi += di * di;
            float dl = (float)g_load[e] - ml; vl += dl * dl;
        }
        vi *= (1.0f / (NEXP - 1));            // unbiased var (ddof=1)
        vl *= (1.0f / (NEXP - 1));
        float loss = 0.01f * (vi / (mi * mi + 1e-10f) + vl / (ml * ml + 1e-10f));
        if (out_size > NN * D) y[NN * D] = loss;
    }
}

// ---------------- launch ------------------------------------------------------
extern "C" void kernel_launch(void* const* d_in, const int* in_sizes, int n_in,
                              void* d_out, int out_size) {
    const float* x    = (const float*)d_in[0];
    const void*  ei   = d_in[1];                 // int32 or int64, runtime-detected
    const float* Wg   = (const float*)d_in[2];
    const float* bg   = (const float*)d_in[3];
    const float* Wexp = (const float*)d_in[4];
    const float* bexp = (const float*)d_in[5];
    float* y = (float*)d_out;

    zero_kernel<<<NN, 256>>>(y, ei);                       // 50000*256 == NN*D exactly
    scatter_kernel<<<(NEDGE * 64) / 256, 256>>>(x, ei);    // 200000 blocks
    gate_kernel<<<(NN + 7) / 8, 256>>>(Wg, bg);
    offsets_kernel<<<1, 32>>>();
    build_lists_kernel<<<(NN * TOPK + 255) / 256, 256>>>();
    int max_tiles = (NN * TOPK + TM - 1) / TM + NEXP;      // upper bound on total tiles
    moe_gemm_kernel<<<dim3(max_tiles, D / TN), 256>>>(Wexp, bexp, y);
    loss_kernel<<<1, 32>>>(y, out_size);
}

// round 3
// speedup vs baseline: 2.4648x; 2.4648x over previous
#include <cuda_runtime.h>
#include <cuda_bf16.h>
#include <cstdint>
#include <math.h>

#define NN 50000
#define NEDGE 800000
#define D 256
#define NEXP 8
#define TOPK 3
#define TM 128          // GEMM M tile
#define TN 128          // GEMM N tile (grid.y = 2 covers D_OUT=256)
#define KC 32           // K staged per iteration
#define SAPAD 36        // padded smem row stride (floats)

// ======================= scratch (static device globals) ======================
__device__ float g_agg[(size_t)NN * D];          // 51.2 MB
__device__ float g_out[(size_t)NN * TOPK * D];   // 153.6 MB raw expert outputs per slot
__device__ float g_Wt[NEXP * D * D];             // W transposed: [e][n][k]
__device__ int   g_deg[NN];
__device__ int   g_rowstart[NN + 1];
__device__ int   g_cursor[NN];
__device__ int   g_elist[NEDGE];
__device__ int   g_gidx[NN * TOPK];
__device__ float g_gval[NN * TOPK];
__device__ int   g_slot[NN * TOPK];              // (node,k) -> perm slot
__device__ float g_imp[NEXP];
__device__ int   g_load[NEXP];
__device__ int   g_pos[NEXP];
__device__ int   g_off[NEXP + 1];
__device__ int   g_toff[NEXP + 1];
__device__ int   g_perm[NN * TOPK];
__device__ int   g_is32;

__device__ __forceinline__ uint32_t f2tf32(float f) {
    uint32_t u; asm("cvt.rna.tf32.f32 %0, %1;" : "=r"(u) : "f"(f)); return u;
}

__device__ __forceinline__ void mma1688(float* c, const uint32_t* a, const uint32_t* b) {
    asm volatile("mma.sync.aligned.m16n8k8.row.col.f32.tf32.tf32.f32 "
        "{%0,%1,%2,%3}, {%4,%5,%6,%7}, {%8,%9}, {%0,%1,%2,%3};"
        : "+f"(c[0]), "+f"(c[1]), "+f"(c[2]), "+f"(c[3])
        : "r"(a[0]), "r"(a[1]), "r"(a[2]), "r"(a[3]), "r"(b[0]), "r"(b[1]));
}

// ---------------- init: zero counters, detect edge dtype ----------------------
__global__ void init_kernel(const void* __restrict__ ei) {
    int i = blockIdx.x * blockDim.x + threadIdx.x;  // 196*256 = 50176
    if (i < NN) g_deg[i] = 0;
    if (i < NEXP) { g_imp[i] = 0.0f; g_load[i] = 0; g_pos[i] = 0; }
    if (i == 0) {
        // int32 buffer read as u64 pairs two indices -> huge value w.h.p.
        const unsigned long long* q = (const unsigned long long*)ei;
        int is32 = 0;
        #pragma unroll
        for (int k = 0; k < 8; k++)
            if (q[k] >= (unsigned long long)NN) is32 = 1;
        g_is32 = is32;
    }
}

__device__ __forceinline__ void load_edge(const void* eiv, int e, int& s, int& dn) {
    if (g_is32) {
        const int* p = (const int*)eiv;
        s = p[e]; dn = p[NEDGE + e];
    } else {
        const long long* p = (const long long*)eiv;
        s = (int)p[e]; dn = (int)p[NEDGE + e];
    }
}

// ---------------- CSR build: histogram / scan / fill --------------------------
__global__ void hist_kernel(const void* __restrict__ eiv) {
    int e = blockIdx.x * blockDim.x + threadIdx.x;  // exactly NEDGE
    int s, dn; load_edge(eiv, e, s, dn);
    atomicAdd(&g_deg[dn], 1);
}

__global__ void scan_kernel() {
    __shared__ int wsum[32];
    __shared__ int s_carry;
    int t = threadIdx.x;  // 1024
    if (t == 0) s_carry = 0;
    __syncthreads();
    for (int base = 0; base < NN; base += 1024) {
        int i = base + t;
        int v = (i < NN) ? g_deg[i] : 0;
        int x = v;
        #pragma unroll
        for (int o = 1; o < 32; o <<= 1) {
            int y = __shfl_up_sync(0xffffffffu, x, o);
            if ((t & 31) >= o) x += y;
        }
        if ((t & 31) == 31) wsum[t >> 5] = x;
        __syncthreads();
        if (t < 32) {
            int w = wsum[t], xx = w;
            #pragma unroll
            for (int o = 1; o < 32; o <<= 1) {
                int y = __shfl_up_sync(0xffffffffu, xx, o);
                if (t >= o) xx += y;
            }
            wsum[t] = xx - w;  // exclusive warp offsets
        }
        __syncthreads();
        int incl = x + wsum[t >> 5] + s_carry;
        if (i < NN) { g_rowstart[i] = incl - v; g_cursor[i] = incl - v; }
        __syncthreads();
        if (t == 1023) s_carry = incl;
        __syncthreads();
    }
    if (t == 0) g_rowstart[NN] = NEDGE;
}

__global__ void fill_kernel(const void* __restrict__ eiv) {
    int e = blockIdx.x * blockDim.x + threadIdx.x;
    int s, dn; load_edge(eiv, e, s, dn);
    int pos = atomicAdd(&g_cursor[dn], 1);
    g_elist[pos] = s;
}

// ---------------- aggregate: warp per node, no fp32 atomics -------------------
__global__ void agg_kernel(const float* __restrict__ x) {
    int w = (blockIdx.x * blockDim.x + threadIdx.x) >> 5;  // node, exact 50000
    int lane = threadIdx.x & 31;
    int start = g_rowstart[w];
    int deg = g_deg[w];
    int c0 = lane * 2, c1 = lane * 2 + 1;  // float4 cols (64 per row)
    float4 a0 = make_float4(0, 0, 0, 0), a1 = make_float4(0, 0, 0, 0);
    const float4* xb = (const float4*)x;
    for (int i = 0; i < deg; i++) {
        int s = g_elist[start + i];
        const float4* xr = xb + (size_t)s * 64;
        float4 v0 = __ldg(xr + c0), v1 = __ldg(xr + c1);
        a0.x += v0.x; a0.y += v0.y; a0.z += v0.z; a0.w += v0.w;
        a1.x += v1.x; a1.y += v1.y; a1.z += v1.z; a1.w += v1.w;
    }
    float4* ar = (float4*)g_agg + (size_t)w * 64;
    ar[c0] = a0; ar[c1] = a1;
}

// ---------------- gate (one warp per node) ------------------------------------
__global__ void gate_kernel(const float* __restrict__ Wg, const float* __restrict__ bg) {
    __shared__ float simp[NEXP];
    __shared__ int   scnt[NEXP];
    int tid = threadIdx.x;
    if (tid < NEXP) { simp[tid] = 0.0f; scnt[tid] = 0; }
    __syncthreads();
    int wid = tid >> 5, lane = tid & 31;
    int n = blockIdx.x * 8 + wid;
    if (n < NN) {
        const float* arow = g_agg + (size_t)n * D;
        float p[NEXP] = {0, 0, 0, 0, 0, 0, 0, 0};
        #pragma unroll
        for (int j = 0; j < 8; j++) {
            float a = arow[j * 32 + lane];
            const float* w = Wg + (size_t)(j * 32 + lane) * NEXP;
            #pragma unroll
            for (int e = 0; e < NEXP; e++) p[e] += a * __ldg(w + e);
        }
        #pragma unroll
        for (int e = 0; e < NEXP; e++) {
            #pragma unroll
            for (int off = 16; off; off >>= 1)
                p[e] += __shfl_xor_sync(0xffffffffu, p[e], off);
            p[e] = fmaxf(p[e] + __ldg(bg + e), 0.0f);
        }
        if (lane == 0) {
            float v[NEXP];
            #pragma unroll
            for (int e = 0; e < NEXP; e++) v[e] = p[e];
            int idx[TOPK]; float val[TOPK];
            #pragma unroll
            for (int k = 0; k < TOPK; k++) {           // strict '>' = lowest index on ties
                int bi = 0; float bv = v[0];
                #pragma unroll
                for (int e = 1; e < NEXP; e++)
                    if (v[e] > bv) { bv = v[e]; bi = e; }
                idx[k] = bi; val[k] = bv; v[bi] = -1.0f;
            }
            float mx = val[0];
            float e0 = __expf(val[0] - mx), e1 = __expf(val[1] - mx), e2 = __expf(val[2] - mx);
            float inv = 1.0f / (e0 + e1 + e2);
            float gv[TOPK] = {e0 * inv, e1 * inv, e2 * inv};
            #pragma unroll
            for (int k = 0; k < TOPK; k++) {
                g_gidx[n * TOPK + k] = idx[k];
                g_gval[n * TOPK + k] = gv[k];
                atomicAdd(&simp[idx[k]], gv[k]);
                atomicAdd(&scnt[idx[k]], 1);
            }
        }
    }
    __syncthreads();
    if (tid < NEXP) {
        atomicAdd(&g_imp[tid], simp[tid]);
        atomicAdd(&g_load[tid], scnt[tid]);
    }
}

// ---------------- per-expert offsets ------------------------------------------
__global__ void offsets_kernel() {
    if (threadIdx.x == 0 && blockIdx.x == 0) {
        int o = 0, t = 0;
        for (int e = 0; e < NEXP; e++) {
            g_off[e] = o; g_toff[e] = t;
            o += g_load[e];
            t += (g_load[e] + TM - 1) / TM;
        }
        g_off[NEXP] = o; g_toff[NEXP] = t;
    }
}

// ---------------- build per-expert node lists (records slot) ------------------
__global__ void build_lists_kernel() {
    __shared__ int lc[NEXP];
    __shared__ int lb[NEXP];
    int tid = threadIdx.x;
    if (tid < NEXP) lc[tid] = 0;
    __syncthreads();
    int p = blockIdx.x * blockDim.x + tid;
    bool valid = (p < NN * TOPK);
    int e = 0, rank = 0, n = 0;
    if (valid) {
        n = p / TOPK;
        e = g_gidx[p];
        rank = atomicAdd(&lc[e], 1);
    }
    __syncthreads();
    if (tid < NEXP) lb[tid] = atomicAdd(&g_pos[tid], lc[tid]);
    __syncthreads();
    if (valid) {
        int slot = g_off[e] + lb[e] + rank;
        g_perm[slot] = n;
        g_slot[p] = slot;
    }
}

// ---------------- transpose W: [e][k][n] -> [e][n][k] -------------------------
__global__ void transW_kernel(const float* __restrict__ W) {
    __shared__ float tl[32][33];
    int e = blockIdx.z, kb = blockIdx.y * 32, nb = blockIdx.x * 32;
    int tx = threadIdx.x, ty = threadIdx.y;  // (32, 8)
    const float* Wb = W + (size_t)e * D * D;
    float* Tb = g_Wt + (size_t)e * D * D;
    #pragma unroll
    for (int j = 0; j < 4; j++)
        tl[ty + 8 * j][tx] = Wb[(size_t)(kb + ty + 8 * j) * D + nb + tx];
    __syncthreads();
    #pragma unroll
    for (int j = 0; j < 4; j++)
        Tb[(size_t)(nb + ty + 8 * j) * D + kb + tx] = tl[tx][ty + 8 * j];
}

// ---------------- mma.sync tf32 grouped GEMM ----------------------------------
// Block: 256 threads = 8 warps, tile 128(M) x 128(N), warps 2(m) x 4(n) -> 64x32.
// A rows gathered via g_perm; B = g_Wt[e] (n-major, k contiguous).
__global__ void __launch_bounds__(256, 2)
moe_gemm_mma(int dummy) {
    __shared__ uint32_t sA[TM * SAPAD];   // [m][k] tf32, padded stride 36
    __shared__ uint32_t sB[TN * SAPAD];   // [n][k] tf32, padded stride 36

    int tile = blockIdx.x;
    if (tile >= g_toff[NEXP]) return;
    int e = 0;
    while (e < NEXP - 1 && tile >= g_toff[e + 1]) e++;
    int mt0 = tile - g_toff[e];
    int base = g_off[e] + mt0 * TM;
    int rows = g_load[e] - mt0 * TM;
    if (rows > TM) rows = TM;
    int n0 = blockIdx.y * TN;

    int tid = threadIdx.x;
    int wid = tid >> 5, lane = tid & 31;
    int gid = lane >> 2, tid4 = lane & 3;
    int wm = wid & 1, wn = wid >> 1;           // warp tile: (wm*64, wn*32)

    // staging ownership: 2 threads per row, 16 floats each
    int r = tid >> 1, half = tid & 1;
    const float4* Af = nullptr;
    if (r < rows) Af = (const float4*)(g_agg + (size_t)g_perm[base + r] * D);
    const float4* Bf = (const float4*)(g_Wt + ((size_t)e * D + n0 + r) * D);

    float acc[4][4][4];
    #pragma unroll
    for (int i = 0; i < 4; i++)
        #pragma unroll
        for (int j = 0; j < 4; j++)
            #pragma unroll
            for (int q = 0; q < 4; q++) acc[i][j][q] = 0.0f;

    for (int c = 0; c < D / KC; c++) {
        // stage A (zero-fill missing rows) and B, converting to tf32
        #pragma unroll
        for (int j = 0; j < 4; j++) {
            int f4 = c * 8 + half * 4 + j;
            float4 va = make_float4(0.f, 0.f, 0.f, 0.f);
            if (Af) va = __ldg(Af + f4);
            uint32_t* pa = &sA[r * SAPAD + half * 16 + j * 4];
            pa[0] = f2tf32(va.x); pa[1] = f2tf32(va.y);
            pa[2] = f2tf32(va.z); pa[3] = f2tf32(va.w);
            float4 vb = __ldg(Bf + f4);
            uint32_t* pb = &sB[r * SAPAD + half * 16 + j * 4];
            pb[0] = f2tf32(vb.x); pb[1] = f2tf32(vb.y);
            pb[2] = f2tf32(vb.z); pb[3] = f2tf32(vb.w);
        }
        __syncthreads();

        #pragma unroll
        for (int ks = 0; ks < 4; ks++) {
            int kk = ks * 8 + tid4;
            uint32_t af[4][4], bf[4][2];
            #pragma unroll
            for (int mi = 0; mi < 4; mi++) {
                int rowa = wm * 64 + mi * 16 + gid;
                af[mi][0] = sA[rowa * SAPAD + kk];
                af[mi][1] = sA[(rowa + 8) * SAPAD + kk];
                af[mi][2] = sA[rowa * SAPAD + kk + 4];
                af[mi][3] = sA[(rowa + 8) * SAPAD + kk + 4];
            }
            #pragma unroll
            for (int ni = 0; ni < 4; ni++) {
                int coln = wn * 32 + ni * 8 + gid;
                bf[ni][0] = sB[coln * SAPAD + kk];
                bf[ni][1] = sB[coln * SAPAD + kk + 4];
            }
            #pragma unroll
            for (int mi = 0; mi < 4; mi++)
                #pragma unroll
                for (int ni = 0; ni < 4; ni++)
                    mma1688(acc[mi][ni], af[mi], bf[ni]);
        }
        __syncthreads();
    }

    // epilogue: direct stores to g_out (no atomics)
    #pragma unroll
    for (int mi = 0; mi < 4; mi++) {
        int mm0 = wm * 64 + mi * 16 + gid;
        int mm1 = mm0 + 8;
        float* r0 = g_out + (size_t)(base + mm0) * D + n0;
        float* r1 = g_out + (size_t)(base + mm1) * D + n0;
        #pragma unroll
        for (int ni = 0; ni < 4; ni++) {
            int col = wn * 32 + ni * 8 + tid4 * 2;
            if (mm0 < rows) *(float2*)(r0 + col) = make_float2(acc[mi][ni][0], acc[mi][ni][1]);
            if (mm1 < rows) *(float2*)(r1 + col) = make_float2(acc[mi][ni][2], acc[mi][ni][3]);
        }
    }
}

// ---------------- combine: y[n] = sum_k g_k * (out_k + b_{e_k}) ---------------
__global__ void combine_kernel(const float* __restrict__ bexp, float* __restrict__ y) {
    int idx = blockIdx.x * blockDim.x + threadIdx.x;  // NN*64 exact
    int n = idx >> 6, c4 = idx & 63;
    float4 acc = make_float4(0, 0, 0, 0);
    #pragma unroll
    for (int k = 0; k < TOPK; k++) {
        int p = n * TOPK + k;
        int slot = g_slot[p];
        float gv = g_gval[p];
        int ex = g_gidx[p];
        float4 o = __ldg((const float4*)(g_out + (size_t)slot * D) + c4);
        float4 b = __ldg((const float4*)(bexp + (size_t)ex * D) + c4);
        acc.x += gv * (o.x + b.x);
        acc.y += gv * (o.y + b.y);
        acc.z += gv * (o.z + b.z);
        acc.w += gv * (o.w + b.w);
    }
    *((float4*)y + (size_t)n * 64 + c4) = acc;
}

// ---------------- loss --------------------------------------------------------
__global__ void loss_kernel(float* __restrict__ y, int out_size) {
    if (threadIdx.x == 0 && blockIdx.x == 0) {
        float mi = 0.0f, ml = 0.0f;
        for (int e = 0; e < NEXP; e++) { mi += g_imp[e]; ml += (float)g_load[e]; }
        mi *= (1.0f / NEXP); ml *= (1.0f / NEXP);
        float vi = 0.0f, vl = 0.0f;
        for (int e = 0; e < NEXP; e++) {
            float di = g_imp[e] - mi;         vi += di * di;
            float dl = (float)g_load[e] - ml; vl += dl * dl;
        }
        vi *= (1.0f / (NEXP - 1));
        vl *= (1.0f / (NEXP - 1));
        float loss = 0.01f * (vi / (mi * mi + 1e-10f) + vl / (ml * ml + 1e-10f));
        if (out_size > NN * D) y[NN * D] = loss;
    }
}

// ---------------- launch ------------------------------------------------------
extern "C" void kernel_launch(void* const* d_in, const int* in_sizes, int n_in,
                              void* d_out, int out_size) {
    const float* x    = (const float*)d_in[0];
    const void*  ei   = d_in[1];
    const float* Wg   = (const float*)d_in[2];
    const float* bg   = (const float*)d_in[3];
    const float* Wexp = (const float*)d_in[4];
    const float* bexp = (const float*)d_in[5];
    float* y = (float*)d_out;

    init_kernel<<<196, 256>>>(ei);
    hist_kernel<<<NEDGE / 256, 256>>>(ei);
    scan_kernel<<<1, 1024>>>();
    fill_kernel<<<NEDGE / 256, 256>>>(ei);
    agg_kernel<<<NN / 8, 256>>>(x);
    transW_kernel<<<dim3(8, 8, NEXP), dim3(32, 8)>>>(Wexp);
    gate_kernel<<<NN / 8, 256>>>(Wg, bg);
    offsets_kernel<<<1, 32>>>();
    build_lists_kernel<<<(NN * TOPK + 255) / 256, 256>>>();
    int max_tiles = (NN * TOPK) / TM + NEXP;  // 1171 + 8 upper bound
    moe_gemm_mma<<<dim3(max_tiles, D / TN), 256>>>(0);
    combine_kernel<<<NN * 64 / 256, 256>>>(bexp, y);
    loss_kernel<<<1, 32>>>(y, out_size);
}

// round 4
// speedup vs baseline: 2.6719x; 1.0840x over previous
#include <cuda_runtime.h>
#include <cuda_bf16.h>
#include <cstdint>
#include <math.h>

#define NN 50000
#define NEDGE 800000
#define D 256
#define NEXP 8
#define TOPK 3
#define TM 128          // GEMM M tile
#define TN 128          // GEMM N tile (grid.y = 2 covers D_OUT=256)
#define KC 32           // K staged per iteration
#define SAPAD 36        // padded smem row stride (words)
#define STAGE_W (TM * SAPAD)            // words per stage (A and B identical)
#define SM_GEMM (4 * STAGE_W * 4)       // 2 A stages + 2 B stages, bytes = 73728

// ======================= scratch (static device globals) ======================
__device__ float    g_agg[(size_t)NN * D];          // 51.2 MB
__device__ float    g_out[(size_t)NN * TOPK * D];   // 153.6 MB expert outputs per slot
__device__ uint32_t g_Wt[NEXP * D * D];             // W transposed [e][n][k], tf32 bits
__device__ int   g_deg[NN];
__device__ int   g_rowstart[NN + 1];
__device__ int   g_cursor[NN];
__device__ int   g_elist[NEDGE];
__device__ int   g_gidx[NN * TOPK];
__device__ float g_gval[NN * TOPK];
__device__ int   g_slot[NN * TOPK];
__device__ float g_imp[NEXP];
__device__ int   g_load[NEXP];
__device__ int   g_pos[NEXP];
__device__ int   g_off[NEXP + 1];
__device__ int   g_toff[NEXP + 1];
__device__ int   g_perm[NN * TOPK];
__device__ int   g_bsum[256];
__device__ int   g_boff[256];
__device__ int   g_is32;

__device__ __forceinline__ uint32_t f2tf32(float f) {
    uint32_t u; asm("cvt.rna.tf32.f32 %0, %1;" : "=r"(u) : "f"(f)); return u;
}
__device__ __forceinline__ void mma1688(float* c, const uint32_t* a, const uint32_t* b) {
    asm volatile("mma.sync.aligned.m16n8k8.row.col.f32.tf32.tf32.f32 "
        "{%0,%1,%2,%3}, {%4,%5,%6,%7}, {%8,%9}, {%0,%1,%2,%3};"
        : "+f"(c[0]), "+f"(c[1]), "+f"(c[2]), "+f"(c[3])
        : "r"(a[0]), "r"(a[1]), "r"(a[2]), "r"(a[3]), "r"(b[0]), "r"(b[1]));
}
__device__ __forceinline__ uint32_t smem_to_u32(const void* p) {
    uint32_t a;
    asm("{ .reg .u64 t; cvta.to.shared.u64 t, %1; cvt.u32.u64 %0, t; }" : "=r"(a) : "l"(p));
    return a;
}
__device__ __forceinline__ void cpasync16(uint32_t dst, const void* src, bool valid) {
    int sz = valid ? 16 : 0;
    asm volatile("cp.async.ca.shared.global [%0], [%1], 16, %2;"
                 :: "r"(dst), "l"(src), "r"(sz));
}
#define CP_COMMIT() asm volatile("cp.async.commit_group;" ::: "memory")
#define CP_WAIT(n)  asm volatile("cp.async.wait_group %0;" :: "n"(n) : "memory")

// ---------------- init: zero counters, detect edge dtype ----------------------
__global__ void init_kernel(const void* __restrict__ ei) {
    int i = blockIdx.x * blockDim.x + threadIdx.x;  // 196*256 = 50176
    if (i < NN) g_deg[i] = 0;
    if (i < NEXP) { g_imp[i] = 0.0f; g_load[i] = 0; g_pos[i] = 0; }
    if (i == 0) {
        const unsigned long long* q = (const unsigned long long*)ei;
        int is32 = 0;
        #pragma unroll
        for (int k = 0; k < 8; k++)
            if (q[k] >= (unsigned long long)NN) is32 = 1;
        g_is32 = is32;
    }
}

__device__ __forceinline__ void load_edge(const void* eiv, int e, int& s, int& dn) {
    if (g_is32) {
        const int* p = (const int*)eiv;
        s = p[e]; dn = p[NEDGE + e];
    } else {
        const long long* p = (const long long*)eiv;
        s = (int)p[e]; dn = (int)p[NEDGE + e];
    }
}

// ---------------- CSR build ---------------------------------------------------
__global__ void hist_kernel(const void* __restrict__ eiv) {
    int e = blockIdx.x * blockDim.x + threadIdx.x;  // exactly NEDGE
    int s, dn; load_edge(eiv, e, s, dn);
    atomicAdd(&g_deg[dn], 1);
}

// scan1: per-block inclusive scan of deg -> g_rowstart (temp), block sums -> g_bsum
__global__ void scan1_kernel() {
    __shared__ int ws[8];
    int b = blockIdx.x, t = threadIdx.x;   // grid 196, block 256
    int i = b * 256 + t;
    int v = (i < NN) ? g_deg[i] : 0;
    int x = v;
    int lane = t & 31;
    #pragma unroll
    for (int o = 1; o < 32; o <<= 1) {
        int y = __shfl_up_sync(0xffffffffu, x, o);
        if (lane >= o) x += y;
    }
    if (lane == 31) ws[t >> 5] = x;
    __syncthreads();
    if (t == 0) {
        int s = 0;
        #pragma unroll
        for (int k = 0; k < 8; k++) { int tmp = ws[k]; ws[k] = s; s += tmp; }
        g_bsum[b] = s;
    }
    __syncthreads();
    int incl = x + ws[t >> 5];
    if (i < NN) g_rowstart[i] = incl;
}

// scan2: exclusive scan of 196 block sums
__global__ void scan2_kernel() {
    __shared__ int sh[256];
    int t = threadIdx.x;
    sh[t] = (t < 196) ? g_bsum[t] : 0;
    __syncthreads();
    if (t == 0) {
        int s = 0;
        for (int k = 0; k < 196; k++) { int tmp = sh[k]; sh[k] = s; s += tmp; }
    }
    __syncthreads();
    if (t < 196) g_boff[t] = sh[t];
}

// scan3: finalize rowstart/cursor
__global__ void scan3_kernel() {
    int b = blockIdx.x, t = threadIdx.x;
    int i = b * 256 + t;
    if (i < NN) {
        int st = g_rowstart[i] + g_boff[b] - g_deg[i];
        g_rowstart[i] = st;
        g_cursor[i] = st;
    }
    if (i == 0) g_rowstart[NN] = NEDGE;
}

__global__ void fill_kernel(const void* __restrict__ eiv) {
    int e = blockIdx.x * blockDim.x + threadIdx.x;
    int s, dn; load_edge(eiv, e, s, dn);
    int pos = atomicAdd(&g_cursor[dn], 1);
    g_elist[pos] = s;
}

// ---------------- aggregate: warp per node, unrolled x2 -----------------------
__global__ void agg_kernel(const float* __restrict__ x) {
    int w = (blockIdx.x * blockDim.x + threadIdx.x) >> 5;  // node, exact 50000
    int lane = threadIdx.x & 31;
    int start = g_rowstart[w];
    int deg = g_deg[w];
    int c0 = lane * 2, c1 = lane * 2 + 1;
    float4 a0 = make_float4(0, 0, 0, 0), a1 = make_float4(0, 0, 0, 0);
    const float4* xb = (const float4*)x;
    int i = 0, end2 = deg & ~1;
    for (; i < end2; i += 2) {
        int s0 = g_elist[start + i], s1 = g_elist[start + i + 1];
        const float4* x0 = xb + (size_t)s0 * 64;
        const float4* x1 = xb + (size_t)s1 * 64;
        float4 v0 = __ldg(x0 + c0), v1 = __ldg(x0 + c1);
        float4 w0 = __ldg(x1 + c0), w1 = __ldg(x1 + c1);
        a0.x += v0.x + w0.x; a0.y += v0.y + w0.y; a0.z += v0.z + w0.z; a0.w += v0.w + w0.w;
        a1.x += v1.x + w1.x; a1.y += v1.y + w1.y; a1.z += v1.z + w1.z; a1.w += v1.w + w1.w;
    }
    if (i < deg) {
        int s0 = g_elist[start + i];
        const float4* x0 = xb + (size_t)s0 * 64;
        float4 v0 = __ldg(x0 + c0), v1 = __ldg(x0 + c1);
        a0.x += v0.x; a0.y += v0.y; a0.z += v0.z; a0.w += v0.w;
        a1.x += v1.x; a1.y += v1.y; a1.z += v1.z; a1.w += v1.w;
    }
    float4* ar = (float4*)g_agg + (size_t)w * 64;
    ar[c0] = a0; ar[c1] = a1;
}

// ---------------- gate (one warp per node) ------------------------------------
__global__ void gate_kernel(const float* __restrict__ Wg, const float* __restrict__ bg) {
    __shared__ float simp[NEXP];
    __shared__ int   scnt[NEXP];
    int tid = threadIdx.x;
    if (tid < NEXP) { simp[tid] = 0.0f; scnt[tid] = 0; }
    __syncthreads();
    int wid = tid >> 5, lane = tid & 31;
    int n = blockIdx.x * 8 + wid;
    if (n < NN) {
        const float* arow = g_agg + (size_t)n * D;
        float p[NEXP] = {0, 0, 0, 0, 0, 0, 0, 0};
        #pragma unroll
        for (int j = 0; j < 8; j++) {
            float a = arow[j * 32 + lane];
            const float* w = Wg + (size_t)(j * 32 + lane) * NEXP;
            #pragma unroll
            for (int e = 0; e < NEXP; e++) p[e] += a * __ldg(w + e);
        }
        #pragma unroll
        for (int e = 0; e < NEXP; e++) {
            #pragma unroll
            for (int off = 16; off; off >>= 1)
                p[e] += __shfl_xor_sync(0xffffffffu, p[e], off);
            p[e] = fmaxf(p[e] + __ldg(bg + e), 0.0f);
        }
        if (lane == 0) {
            float v[NEXP];
            #pragma unroll
            for (int e = 0; e < NEXP; e++) v[e] = p[e];
            int idx[TOPK]; float val[TOPK];
            #pragma unroll
            for (int k = 0; k < TOPK; k++) {           // strict '>' = lowest index on ties
                int bi = 0; float bv = v[0];
                #pragma unroll
                for (int e = 1; e < NEXP; e++)
                    if (v[e] > bv) { bv = v[e]; bi = e; }
                idx[k] = bi; val[k] = bv; v[bi] = -1.0f;
            }
            float mx = val[0];
            float e0 = __expf(val[0] - mx), e1 = __expf(val[1] - mx), e2 = __expf(val[2] - mx);
            float inv = 1.0f / (e0 + e1 + e2);
            float gv[TOPK] = {e0 * inv, e1 * inv, e2 * inv};
            #pragma unroll
            for (int k = 0; k < TOPK; k++) {
                g_gidx[n * TOPK + k] = idx[k];
                g_gval[n * TOPK + k] = gv[k];
                atomicAdd(&simp[idx[k]], gv[k]);
                atomicAdd(&scnt[idx[k]], 1);
            }
        }
    }
    __syncthreads();
    if (tid < NEXP) {
        atomicAdd(&g_imp[tid], simp[tid]);
        atomicAdd(&g_load[tid], scnt[tid]);
    }
}

// ---------------- per-expert offsets ------------------------------------------
__global__ void offsets_kernel() {
    if (threadIdx.x == 0 && blockIdx.x == 0) {
        int o = 0, t = 0;
        for (int e = 0; e < NEXP; e++) {
            g_off[e] = o; g_toff[e] = t;
            o += g_load[e];
            t += (g_load[e] + TM - 1) / TM;
        }
        g_off[NEXP] = o; g_toff[NEXP] = t;
    }
}

// ---------------- build per-expert node lists ---------------------------------
__global__ void build_lists_kernel() {
    __shared__ int lc[NEXP];
    __shared__ int lb[NEXP];
    int tid = threadIdx.x;
    if (tid < NEXP) lc[tid] = 0;
    __syncthreads();
    int p = blockIdx.x * blockDim.x + tid;
    bool valid = (p < NN * TOPK);
    int e = 0, rank = 0, n = 0;
    if (valid) {
        n = p / TOPK;
        e = g_gidx[p];
        rank = atomicAdd(&lc[e], 1);
    }
    __syncthreads();
    if (tid < NEXP) lb[tid] = atomicAdd(&g_pos[tid], lc[tid]);
    __syncthreads();
    if (valid) {
        int slot = g_off[e] + lb[e] + rank;
        g_perm[slot] = n;
        g_slot[p] = slot;
    }
}

// ---------------- transpose W -> tf32 bits: [e][k][n] -> [e][n][k] ------------
__global__ void transW_kernel(const float* __restrict__ W) {
    __shared__ float tl[32][33];
    int e = blockIdx.z, kb = blockIdx.y * 32, nb = blockIdx.x * 32;
    int tx = threadIdx.x, ty = threadIdx.y;  // (32, 8)
    const float* Wb = W + (size_t)e * D * D;
    uint32_t* Tb = g_Wt + (size_t)e * D * D;
    #pragma unroll
    for (int j = 0; j < 4; j++)
        tl[ty + 8 * j][tx] = Wb[(size_t)(kb + ty + 8 * j) * D + nb + tx];
    __syncthreads();
    #pragma unroll
    for (int j = 0; j < 4; j++)
        Tb[(size_t)(nb + ty + 8 * j) * D + kb + tx] = f2tf32(tl[tx][ty + 8 * j]);
}

// ---------------- mma.sync tf32 grouped GEMM, cp.async double-buffered --------
__global__ void __launch_bounds__(256, 2)
moe_gemm_mma() {
    extern __shared__ uint32_t smem[];
    uint32_t* sA = smem;                 // [2][TM*SAPAD] raw fp32 bits
    uint32_t* sB = smem + 2 * STAGE_W;   // [2][TN*SAPAD] tf32 bits

    int tile = blockIdx.x;
    if (tile >= g_toff[NEXP]) return;
    int e = 0;
    while (e < NEXP - 1 && tile >= g_toff[e + 1]) e++;
    int mt0 = tile - g_toff[e];
    int base = g_off[e] + mt0 * TM;
    int rows = g_load[e] - mt0 * TM;
    if (rows > TM) rows = TM;
    int n0 = blockIdx.y * TN;

    int tid = threadIdx.x;
    int wid = tid >> 5, lane = tid & 31;
    int gid = lane >> 2, tid4 = lane & 3;
    int wm = wid & 1, wn = wid >> 1;

    int r = tid >> 1, half = tid & 1;
    const float4* Af = nullptr;
    if (r < rows) Af = (const float4*)(g_agg + (size_t)g_perm[base + r] * D);
    const uint4* Bf = (const uint4*)(g_Wt + ((size_t)e * D + n0 + r) * D);

    uint32_t sbase = smem_to_u32(smem);
    uint32_t aAddr = sbase + (uint32_t)((r * SAPAD + half * 16) * 4);
    uint32_t bAddr = sbase + (uint32_t)((2 * STAGE_W + r * SAPAD + half * 16) * 4);

    float acc[4][4][4];
    #pragma unroll
    for (int i = 0; i < 4; i++)
        #pragma unroll
        for (int j = 0; j < 4; j++)
            #pragma unroll
            for (int q = 0; q < 4; q++) acc[i][j][q] = 0.0f;

    // prologue: stage chunk 0 into buffer 0
    {
        #pragma unroll
        for (int j = 0; j < 4; j++) {
            int f4 = half * 4 + j;
            cpasync16(aAddr + j * 16, Af ? (const void*)(Af + f4) : (const void*)g_agg, Af != nullptr);
            cpasync16(bAddr + j * 16, (const void*)(Bf + f4), true);
        }
        CP_COMMIT();
    }

    for (int c = 0; c < D / KC; c++) {
        if (c < D / KC - 1) {
            int buf = (c + 1) & 1;
            #pragma unroll
            for (int j = 0; j < 4; j++) {
                int f4 = (c + 1) * 8 + half * 4 + j;
                cpasync16(aAddr + (uint32_t)(buf * STAGE_W * 4) + j * 16,
                          Af ? (const void*)(Af + f4) : (const void*)g_agg, Af != nullptr);
                cpasync16(bAddr + (uint32_t)(buf * STAGE_W * 4) + j * 16,
                          (const void*)(Bf + f4), true);
            }
            CP_COMMIT();
            CP_WAIT(1);
        } else {
            CP_WAIT(0);
        }
        __syncthreads();

        const uint32_t* A = sA + (c & 1) * STAGE_W;
        const uint32_t* B = sB + (c & 1) * STAGE_W;
        #pragma unroll
        for (int ks = 0; ks < 4; ks++) {
            int kk = ks * 8 + tid4;
            uint32_t af[4][4], bf[4][2];
            #pragma unroll
            for (int mi = 0; mi < 4; mi++) {
                int rowa = wm * 64 + mi * 16 + gid;
                af[mi][0] = f2tf32(__uint_as_float(A[rowa * SAPAD + kk]));
                af[mi][1] = f2tf32(__uint_as_float(A[(rowa + 8) * SAPAD + kk]));
                af[mi][2] = f2tf32(__uint_as_float(A[rowa * SAPAD + kk + 4]));
                af[mi][3] = f2tf32(__uint_as_float(A[(rowa + 8) * SAPAD + kk + 4]));
            }
            #pragma unroll
            for (int ni = 0; ni < 4; ni++) {
                int coln = wn * 32 + ni * 8 + gid;
                bf[ni][0] = B[coln * SAPAD + kk];
                bf[ni][1] = B[coln * SAPAD + kk + 4];
            }
            #pragma unroll
            for (int mi = 0; mi < 4; mi++)
                #pragma unroll
                for (int ni = 0; ni < 4; ni++)
                    mma1688(acc[mi][ni], af[mi], bf[ni]);
        }
        __syncthreads();
    }

    // epilogue: direct stores to g_out (no atomics)
    #pragma unroll
    for (int mi = 0; mi < 4; mi++) {
        int mm0 = wm * 64 + mi * 16 + gid;
        int mm1 = mm0 + 8;
        float* r0 = g_out + (size_t)(base + mm0) * D + n0;
        float* r1 = g_out + (size_t)(base + mm1) * D + n0;
        #pragma unroll
        for (int ni = 0; ni < 4; ni++) {
            int col = wn * 32 + ni * 8 + tid4 * 2;
            if (mm0 < rows) *(float2*)(r0 + col) = make_float2(acc[mi][ni][0], acc[mi][ni][1]);
            if (mm1 < rows) *(float2*)(r1 + col) = make_float2(acc[mi][ni][2], acc[mi][ni][3]);
        }
    }
}

// ---------------- combine: y[n] = sum_k g_k * (out_k + b_{e_k}) ---------------
__global__ void combine_kernel(const float* __restrict__ bexp, float* __restrict__ y) {
    int idx = blockIdx.x * blockDim.x + threadIdx.x;  // NN*64 exact
    int n = idx >> 6, c4 = idx & 63;
    float4 acc = make_float4(0, 0, 0, 0);
    #pragma unroll
    for (int k = 0; k < TOPK; k++) {
        int p = n * TOPK + k;
        int slot = g_slot[p];
        float gv = g_gval[p];
        int ex = g_gidx[p];
        float4 o = __ldg((const float4*)(g_out + (size_t)slot * D) + c4);
        float4 b = __ldg((const float4*)(bexp + (size_t)ex * D) + c4);
        acc.x += gv * (o.x + b.x);
        acc.y += gv * (o.y + b.y);
        acc.z += gv * (o.z + b.z);
        acc.w += gv * (o.w + b.w);
    }
    *((float4*)y + (size_t)n * 64 + c4) = acc;
}

// ---------------- loss --------------------------------------------------------
__global__ void loss_kernel(float* __restrict__ y, int out_size) {
    if (threadIdx.x == 0 && blockIdx.x == 0) {
        float mi = 0.0f, ml = 0.0f;
        for (int e = 0; e < NEXP; e++) { mi += g_imp[e]; ml += (float)g_load[e]; }
        mi *= (1.0f / NEXP); ml *= (1.0f / NEXP);
        float vi = 0.0f, vl = 0.0f;
        for (int e = 0; e < NEXP; e++) {
            float di = g_imp[e] - mi;         vi += di * di;
            float dl = (float)g_load[e] - ml; vl += dl * dl;
        }
        vi *= (1.0f / (NEXP - 1));
        vl *= (1.0f / (NEXP - 1));
        float loss = 0.01f * (vi / (mi * mi + 1e-10f) + vl / (ml * ml + 1e-10f));
        if (out_size > NN * D) y[NN * D] = loss;
    }
}

// ---------------- launch ------------------------------------------------------
extern "C" void kernel_launch(void* const* d_in, const int* in_sizes, int n_in,
                              void* d_out, int out_size) {
    const float* x    = (const float*)d_in[0];
    const void*  ei   = d_in[1];
    const float* Wg   = (const float*)d_in[2];
    const float* bg   = (const float*)d_in[3];
    const float* Wexp = (const float*)d_in[4];
    const float* bexp = (const float*)d_in[5];
    float* y = (float*)d_out;

    cudaFuncSetAttribute(moe_gemm_mma, cudaFuncAttributeMaxDynamicSharedMemorySize, SM_GEMM);

    init_kernel<<<196, 256>>>(ei);
    hist_kernel<<<NEDGE / 256, 256>>>(ei);
    scan1_kernel<<<196, 256>>>();
    scan2_kernel<<<1, 256>>>();
    scan3_kernel<<<196, 256>>>();
    fill_kernel<<<NEDGE / 256, 256>>>(ei);
    agg_kernel<<<NN / 8, 256>>>(x);
    transW_kernel<<<dim3(8, 8, NEXP), dim3(32, 8)>>>(Wexp);
    gate_kernel<<<NN / 8, 256>>>(Wg, bg);
    offsets_kernel<<<1, 32>>>();
    build_lists_kernel<<<(NN * TOPK + 255) / 256, 256>>>();
    int max_tiles = (NN * TOPK) / TM + NEXP;  // upper bound on total tiles
    moe_gemm_mma<<<dim3(max_tiles, D / TN), 256, SM_GEMM>>>();
    combine_kernel<<<NN * 64 / 256, 256>>>(bexp, y);
    loss_kernel<<<1, 32>>>(y, out_size);
}